// round 5
// baseline (speedup 1.0000x reference)
#include <cuda_runtime.h>
#include <cuda_bf16.h>
#include <cstdint>

// Problem constants
#define BB   4
#define NTOK 4096
#define PD   1024
#define DD   16
#define NC   (NTOK / DD)
#define GK   1024                 // K of both GEMMs
#define GM   (BB * NTOK)          // 16384 rows

// ---------------------------------------------------------------------------
// Scratch (device globals: allocation-free rule)
// ---------------------------------------------------------------------------
__device__ float g_P[(size_t)GM * 2048];              // P  (128 MiB)
__device__ __nv_bfloat16 g_Ah[(size_t)GM * GK];       // x hi   (32 MiB)
__device__ __nv_bfloat16 g_Al[(size_t)GM * GK];       // x lo
__device__ __nv_bfloat16 g_Qh[(size_t)GM * 1024];     // Q hi
__device__ __nv_bfloat16 g_Ql[(size_t)GM * 1024];     // Q lo
__device__ __nv_bfloat16 g_B1h[2048 * GK];            // W_r^T hi [N][K]
__device__ __nv_bfloat16 g_B1l[2048 * GK];
__device__ __nv_bfloat16 g_B2h[1024 * GK];            // W_w^T hi [N][K]
__device__ __nv_bfloat16 g_B2l[1024 * GK];

// ---------------------------------------------------------------------------
// PTX helpers (plain sm_103-legal only: cp.async / ldmatrix / mma.sync)
// ---------------------------------------------------------------------------
__device__ __forceinline__ uint32_t smem_to_u32(const void* p) {
    uint32_t a;
    asm("{ .reg .u64 t; cvta.to.shared.u64 t, %1; cvt.u32.u64 %0, t; }"
        : "=r"(a) : "l"(p));
    return a;
}

#define CP_ASYNC16(saddr, gptr) \
    asm volatile("cp.async.cg.shared.global [%0], [%1], 16;" \
                 :: "r"(saddr), "l"(gptr))
#define CP_COMMIT() asm volatile("cp.async.commit_group;" ::: "memory")
#define CP_WAIT(n)  asm volatile("cp.async.wait_group %0;" :: "n"(n) : "memory")

__device__ __forceinline__ void ldsm_x4(uint32_t (&r)[4], uint32_t addr) {
    asm volatile("ldmatrix.sync.aligned.m8n8.x4.shared.b16 {%0,%1,%2,%3}, [%4];"
                 : "=r"(r[0]), "=r"(r[1]), "=r"(r[2]), "=r"(r[3]) : "r"(addr));
}

__device__ __forceinline__ void mma_bf16(float (&d)[4], const uint32_t (&a)[4],
                                         uint32_t b0, uint32_t b1) {
    asm volatile(
        "mma.sync.aligned.m16n8k16.row.col.f32.bf16.bf16.f32 "
        "{%0,%1,%2,%3}, {%4,%5,%6,%7}, {%8,%9}, {%0,%1,%2,%3};"
        : "+f"(d[0]), "+f"(d[1]), "+f"(d[2]), "+f"(d[3])
        : "r"(a[0]), "r"(a[1]), "r"(a[2]), "r"(a[3]), "r"(b0), "r"(b1));
}

// Swizzled byte offset inside a [rows][64 B] tile.
// 8 consecutive rows at fixed kbyte map to 8 distinct 16B slots mod 128B.
__device__ __forceinline__ uint32_t tile_off(int row, int kbyte) {
    return (uint32_t)(row * 64 + (kbyte ^ (((row >> 1) & 3) << 4)));
}

// ---------------------------------------------------------------------------
// Prep kernels
// ---------------------------------------------------------------------------
__global__ void split_x_kernel(const float* __restrict__ X,
                               __nv_bfloat16* __restrict__ H,
                               __nv_bfloat16* __restrict__ L)
{
    size_t i = (size_t)blockIdx.x * blockDim.x + threadIdx.x;   // float4 idx
    float4 v = ((const float4*)X)[i];
    __nv_bfloat16 h[4], l[4];
    float f[4] = {v.x, v.y, v.z, v.w};
    #pragma unroll
    for (int q = 0; q < 4; q++) {
        h[q] = __float2bfloat16(f[q]);
        l[q] = __float2bfloat16(f[q] - __bfloat162float(h[q]));
    }
    *(uint64_t*)(H + i * 4) = *(uint64_t*)h;
    *(uint64_t*)(L + i * 4) = *(uint64_t*)l;
}

__global__ void transpose_split_kernel(const float* __restrict__ W,
                                       __nv_bfloat16* __restrict__ Bh,
                                       __nv_bfloat16* __restrict__ Bl,
                                       int K, int N)
{
    __shared__ float t[32][33];
    const int n0 = blockIdx.x * 32, k0 = blockIdx.y * 32;
    const int tx = threadIdx.x, ty = threadIdx.y;
    #pragma unroll
    for (int i = 0; i < 32; i += 8)
        t[ty + i][tx] = W[(size_t)(k0 + ty + i) * N + n0 + tx];
    __syncthreads();
    #pragma unroll
    for (int i = 0; i < 32; i += 8) {
        float v = t[tx][ty + i];
        __nv_bfloat16 h = __float2bfloat16(v);
        __nv_bfloat16 l = __float2bfloat16(v - __bfloat162float(h));
        size_t o = (size_t)(n0 + ty + i) * K + (k0 + tx);
        Bh[o] = h; Bl[o] = l;
    }
}

// ---------------------------------------------------------------------------
// bf16-split GEMM via mma.sync:  C[M,N] = A @ B^T + bias
//   A: Ah/Al [M][K] bf16 row-major;  B: Bh/Bl [N][K] bf16 row-major
//   3 passes: Ah*Bh + Ah*Bl + Al*Bh (fp32 accum)
// Tile 128x256xBK32, 3-stage cp.async pipeline, 512 threads (4m x 4n warps,
// warp tile 32x64).
// ---------------------------------------------------------------------------
#define TM 128
#define TN 256
#define BKC 32
#define STAGE_BYTES 49152            // Ah/Al 8KB each + Bh/Bl 16KB each
#define OFF_AH 0
#define OFF_AL 8192
#define OFF_BH 16384
#define OFF_BL 32768
#define NSTAGE 3
#define GEMM_SMEM (NSTAGE * STAGE_BYTES)   // 147456
#define NCHUNK (GK / BKC)

__device__ __forceinline__ void issue_stage(uint32_t sbase,
    const __nv_bfloat16* __restrict__ Ah, const __nv_bfloat16* __restrict__ Al,
    const __nv_bfloat16* __restrict__ Bh, const __nv_bfloat16* __restrict__ Bl,
    int k0, int tid)
{
    // A tiles: 128 rows x 64B (h and l): 512 x 16B each
    {
        int row = tid >> 2;                 // 0..127
        int kc  = tid & 3;
        uint32_t off = tile_off(row, kc * 16);
        size_t g = (size_t)row * GK + k0 + kc * 8;
        CP_ASYNC16(sbase + OFF_AH + off, Ah + g);
        CP_ASYNC16(sbase + OFF_AL + off, Al + g);
    }
    // B tiles: 256 rows x 64B (h and l): 1024 x 16B each
    #pragma unroll
    for (int h = 0; h < 2; h++) {
        int idx = tid + h * 512;            // 0..1023
        int row = idx >> 2;                 // 0..255
        int kc  = idx & 3;
        uint32_t off = tile_off(row, kc * 16);
        size_t g = (size_t)row * GK + k0 + kc * 8;
        CP_ASYNC16(sbase + OFF_BH + off, Bh + g);
        CP_ASYNC16(sbase + OFF_BL + off, Bl + g);
    }
}

__global__ __launch_bounds__(512, 1)
void gemm_mma_kernel(const __nv_bfloat16* __restrict__ Ah,
                     const __nv_bfloat16* __restrict__ Al,
                     const __nv_bfloat16* __restrict__ Bh,
                     const __nv_bfloat16* __restrict__ Bl,
                     const float* __restrict__ bias,
                     float* __restrict__ C, int N)
{
    extern __shared__ char smem[];
    const uint32_t sbase = smem_to_u32(smem);
    const int tid  = threadIdx.x;
    const int lane = tid & 31;
    const int wid  = tid >> 5;          // 0..15
    const int wm   = wid & 3;           // 0..3  (32-row slice)
    const int wn   = wid >> 2;          // 0..3  (64-col slice)
    const int m0 = blockIdx.y * TM;
    const int n0 = blockIdx.x * TN;

    const __nv_bfloat16* Ahb = Ah + (size_t)m0 * GK;
    const __nv_bfloat16* Alb = Al + (size_t)m0 * GK;
    const __nv_bfloat16* Bhb = Bh + (size_t)n0 * GK;
    const __nv_bfloat16* Blb = Bl + (size_t)n0 * GK;

    float acc[2][8][4];
    #pragma unroll
    for (int i = 0; i < 2; i++)
        #pragma unroll
        for (int j = 0; j < 8; j++)
            #pragma unroll
            for (int q = 0; q < 4; q++) acc[i][j][q] = 0.f;

    // prologue: stages 0,1
    issue_stage(sbase + 0 * STAGE_BYTES, Ahb, Alb, Bhb, Blb, 0, tid);
    CP_COMMIT();
    issue_stage(sbase + 1 * STAGE_BYTES, Ahb, Alb, Bhb, Blb, BKC, tid);
    CP_COMMIT();

    // ldmatrix lane addressing pieces
    const int lrow = lane & 15;
    const int lcol = (lane >> 4) * 16;

    for (int c = 0; c < NCHUNK; c++) {
        if (c + 2 < NCHUNK) CP_WAIT(1); else CP_WAIT(0);
        __syncthreads();

        if (c + 2 < NCHUNK) {
            issue_stage(sbase + ((c + 2) % NSTAGE) * STAGE_BYTES,
                        Ahb, Alb, Bhb, Blb, (c + 2) * BKC, tid);
            CP_COMMIT();
        }

        const uint32_t sb = sbase + (c % NSTAGE) * STAGE_BYTES;

        #pragma unroll
        for (int ks = 0; ks < 2; ks++) {
            const int kb = ks * 32 + lcol;
            uint32_t ah[2][4], al[2][4];
            #pragma unroll
            for (int mt = 0; mt < 2; mt++) {
                uint32_t o = tile_off(wm * 32 + mt * 16 + lrow, kb);
                ldsm_x4(ah[mt], sb + OFF_AH + o);
                ldsm_x4(al[mt], sb + OFF_AL + o);
            }
            uint32_t bh[4][4], bl[4][4];
            #pragma unroll
            for (int ng = 0; ng < 4; ng++) {
                uint32_t o = tile_off(wn * 64 + ng * 16 + lrow, kb);
                ldsm_x4(bh[ng], sb + OFF_BH + o);
                ldsm_x4(bl[ng], sb + OFF_BL + o);
            }
            #pragma unroll
            for (int mt = 0; mt < 2; mt++)
                #pragma unroll
                for (int nt = 0; nt < 8; nt++)
                    mma_bf16(acc[mt][nt], ah[mt],
                             bh[nt >> 1][nt & 1], bh[nt >> 1][(nt & 1) + 2]);
            #pragma unroll
            for (int mt = 0; mt < 2; mt++)
                #pragma unroll
                for (int nt = 0; nt < 8; nt++)
                    mma_bf16(acc[mt][nt], ah[mt],
                             bl[nt >> 1][nt & 1], bl[nt >> 1][(nt & 1) + 2]);
            #pragma unroll
            for (int mt = 0; mt < 2; mt++)
                #pragma unroll
                for (int nt = 0; nt < 8; nt++)
                    mma_bf16(acc[mt][nt], al[mt],
                             bh[nt >> 1][nt & 1], bh[nt >> 1][(nt & 1) + 2]);
        }
    }

    // epilogue
    float* Cblk = C + (size_t)m0 * N + n0;
    #pragma unroll
    for (int mt = 0; mt < 2; mt++) {
        #pragma unroll
        for (int nt = 0; nt < 8; nt++) {
            int r  = wm * 32 + mt * 16 + (lane >> 2);
            int cc = wn * 64 + nt * 8 + (lane & 3) * 2;
            float b0 = __ldg(&bias[n0 + cc]);
            float b1 = __ldg(&bias[n0 + cc + 1]);
            float2 v0 = {acc[mt][nt][0] + b0, acc[mt][nt][1] + b1};
            float2 v1 = {acc[mt][nt][2] + b0, acc[mt][nt][3] + b1};
            *(float2*)(Cblk + (size_t)r * N + cc) = v0;
            *(float2*)(Cblk + (size_t)(r + 8) * N + cc) = v1;
        }
    }
}

// ---------------------------------------------------------------------------
// Middle kernel (math verified; emits Q split into bf16 hi/lo):
//   p[n,m,s]  = softmax_m( P[b,n,0,m,s] )
//   Qg[n,d,s] = sum_{m<d} p[n,m,s] * P1[(n+m+1)%N, d-1-m, s];  masked last chunk
// ---------------------------------------------------------------------------
__global__ __launch_bounds__(256)
void middle_kernel(const float* __restrict__ P,
                   __nv_bfloat16* __restrict__ Qh,
                   __nv_bfloat16* __restrict__ Ql)
{
    __shared__ float sR[30][16][17];

    const int sg = blockIdx.x;
    const int c  = blockIdx.y;
    const int b  = blockIdx.z;
    const int tid = threadIdx.x;
    const int sl = tid & 15;
    const int t  = tid >> 4;

    const long Pbase = (long)b * NTOK * 2048;

    for (int i = tid; i < 30 * 16 * 16; i += 256) {
        int s16 = i & 15;
        int d   = (i >> 4) & 15;
        int u   = i >> 8;
        int tokn = c * DD + u + 1;
        if (tokn >= NTOK) tokn -= NTOK;
        sR[u][d][s16] =
            P[Pbase + (long)tokn * 2048 + 1024 + d * 64 + sg * 16 + s16];
    }
    __syncthreads();

    const int n = c * DD + t;
    const float* p0 = P + Pbase + (long)n * 2048 + sg * 16 + sl;

    float v[16];
    float mx = -1e30f;
    #pragma unroll
    for (int d = 0; d < 16; d++) { v[d] = p0[d * 64]; mx = fmaxf(mx, v[d]); }
    float sum = 0.f;
    #pragma unroll
    for (int d = 0; d < 16; d++) { v[d] = __expf(v[d] - mx); sum += v[d]; }
    const float inv = 1.f / sum;
    #pragma unroll
    for (int d = 0; d < 16; d++) v[d] *= inv;

    const size_t qbase = ((size_t)b * NTOK + n) * 1024 + sg * 16 + sl;
    const bool lastc = (c == NC - 1);

    #pragma unroll
    for (int d = 0; d < 16; d++) {
        float acc = 0.f;
        #pragma unroll
        for (int m = 0; m < d; m++)
            acc += v[m] * sR[t + m][d - 1 - m][sl];
        if (lastc && (t + d >= DD)) acc = 0.f;
        __nv_bfloat16 h = __float2bfloat16(acc);
        __nv_bfloat16 l = __float2bfloat16(acc - __bfloat162float(h));
        Qh[qbase + d * 64] = h;
        Ql[qbase + d * 64] = l;
    }
}

// ---------------------------------------------------------------------------
extern "C" void kernel_launch(void* const* d_in, const int* in_sizes, int n_in,
                              void* d_out, int out_size)
{
    const float* x  = (const float*)d_in[0];   // [4,4096,1024]
    const float* Wr = (const float*)d_in[1];   // [1024,2048]
    const float* br = (const float*)d_in[2];   // [2048]
    const float* Ww = (const float*)d_in[3];   // [1024,1024]
    const float* bw = (const float*)d_in[4];   // [1024]
    float* out = (float*)d_out;                // [4,4096,1024]

    float* P;
    __nv_bfloat16 *Ah, *Al, *Qh, *Ql, *B1h, *B1l, *B2h, *B2l;
    cudaGetSymbolAddress((void**)&P,   g_P);
    cudaGetSymbolAddress((void**)&Ah,  g_Ah);
    cudaGetSymbolAddress((void**)&Al,  g_Al);
    cudaGetSymbolAddress((void**)&Qh,  g_Qh);
    cudaGetSymbolAddress((void**)&Ql,  g_Ql);
    cudaGetSymbolAddress((void**)&B1h, g_B1h);
    cudaGetSymbolAddress((void**)&B1l, g_B1l);
    cudaGetSymbolAddress((void**)&B2h, g_B2h);
    cudaGetSymbolAddress((void**)&B2l, g_B2l);

    cudaFuncSetAttribute(gemm_mma_kernel,
                         cudaFuncAttributeMaxDynamicSharedMemorySize, GEMM_SMEM);

    // Prep: split activations + weights
    split_x_kernel<<<(GM * GK / 4) / 256, 256>>>(x, Ah, Al);
    {
        dim3 blk(32, 8);
        transpose_split_kernel<<<dim3(2048 / 32, 1024 / 32), blk>>>(Wr, B1h, B1l, GK, 2048);
        transpose_split_kernel<<<dim3(1024 / 32, 1024 / 32), blk>>>(Ww, B2h, B2l, GK, 1024);
    }
    // GEMM1: P = x @ W_r + b_r   [16384,1024] x [1024,2048]
    {
        dim3 grid(2048 / TN, GM / TM);
        gemm_mma_kernel<<<grid, 512, GEMM_SMEM>>>(Ah, Al, B1h, B1l, br, P, 2048);
    }
    // Middle: softmax + triangular conv -> Qh/Ql (bf16 split)
    {
        dim3 grid(4, NC, BB);
        middle_kernel<<<grid, 256>>>(P, Qh, Ql);
    }
    // GEMM2: out = Q @ W_w + b_w   [16384,1024] x [1024,1024]
    {
        dim3 grid(1024 / TN, GM / TM);
        gemm_mma_kernel<<<grid, 512, GEMM_SMEM>>>(Qh, Ql, B2h, B2l, bw, out, 1024);
    }
}

// round 6
// speedup vs baseline: 1.4153x; 1.4153x over previous
#include <cuda_runtime.h>
#include <cuda_bf16.h>
#include <cuda_fp16.h>
#include <cstdint>

// Problem constants
#define BB   4
#define NTOK 4096
#define PD   1024
#define DD   16
#define NC   (NTOK / DD)
#define GK   1024                 // K of both GEMMs
#define GM   (BB * NTOK)          // 16384 rows

// ---------------------------------------------------------------------------
// Scratch (device globals: allocation-free rule)
// ---------------------------------------------------------------------------
__device__ float g_P[(size_t)GM * 2048];        // P  (128 MiB)
__device__ __half g_Ah[(size_t)GM * GK];        // x hi   (32 MiB)
__device__ __half g_Al[(size_t)GM * GK];        // x lo
__device__ __half g_Qh[(size_t)GM * 1024];      // Q hi
__device__ __half g_Ql[(size_t)GM * 1024];      // Q lo
__device__ __half g_B1[2048 * GK];              // W_r^T fp16 [N][K]
__device__ __half g_B2[1024 * GK];              // W_w^T fp16 [N][K]

// ---------------------------------------------------------------------------
// PTX helpers (plain sm_103-legal only: cp.async / ldmatrix / mma.sync)
// ---------------------------------------------------------------------------
__device__ __forceinline__ uint32_t smem_to_u32(const void* p) {
    uint32_t a;
    asm("{ .reg .u64 t; cvta.to.shared.u64 t, %1; cvt.u32.u64 %0, t; }"
        : "=r"(a) : "l"(p));
    return a;
}

#define CP_ASYNC16(saddr, gptr) \
    asm volatile("cp.async.cg.shared.global [%0], [%1], 16;" \
                 :: "r"(saddr), "l"(gptr))
#define CP_COMMIT() asm volatile("cp.async.commit_group;" ::: "memory")
#define CP_WAIT(n)  asm volatile("cp.async.wait_group %0;" :: "n"(n) : "memory")

__device__ __forceinline__ void ldsm_x4(uint32_t (&r)[4], uint32_t addr) {
    asm volatile("ldmatrix.sync.aligned.m8n8.x4.shared.b16 {%0,%1,%2,%3}, [%4];"
                 : "=r"(r[0]), "=r"(r[1]), "=r"(r[2]), "=r"(r[3]) : "r"(addr));
}

__device__ __forceinline__ void mma_f16(float (&d)[4], const uint32_t (&a)[4],
                                        uint32_t b0, uint32_t b1) {
    asm volatile(
        "mma.sync.aligned.m16n8k16.row.col.f32.f16.f16.f32 "
        "{%0,%1,%2,%3}, {%4,%5,%6,%7}, {%8,%9}, {%0,%1,%2,%3};"
        : "+f"(d[0]), "+f"(d[1]), "+f"(d[2]), "+f"(d[3])
        : "r"(a[0]), "r"(a[1]), "r"(a[2]), "r"(a[3]), "r"(b0), "r"(b1));
}

// Swizzled byte offset inside a [rows][64 B] tile.
// 8 consecutive rows at fixed kbyte map to 8 distinct 16B slots mod 128B.
__device__ __forceinline__ uint32_t tile_off(int row, int kbyte) {
    return (uint32_t)(row * 64 + (kbyte ^ (((row >> 1) & 3) << 4)));
}

// ---------------------------------------------------------------------------
// Prep kernels
// ---------------------------------------------------------------------------
__global__ void split_x_kernel(const float* __restrict__ X,
                               __half* __restrict__ H,
                               __half* __restrict__ L)
{
    size_t i = (size_t)blockIdx.x * blockDim.x + threadIdx.x;   // float4 idx
    float4 v = ((const float4*)X)[i];
    __half h[4], l[4];
    float f[4] = {v.x, v.y, v.z, v.w};
    #pragma unroll
    for (int q = 0; q < 4; q++) {
        h[q] = __float2half_rn(f[q]);
        l[q] = __float2half_rn(f[q] - __half2float(h[q]));
    }
    *(uint64_t*)(H + i * 4) = *(uint64_t*)h;
    *(uint64_t*)(L + i * 4) = *(uint64_t*)l;
}

// W [K][N] fp32 -> B [N][K] fp16 (transposed, single rounding)
__global__ void transpose_h_kernel(const float* __restrict__ W,
                                   __half* __restrict__ Bh,
                                   int K, int N)
{
    __shared__ float t[32][33];
    const int n0 = blockIdx.x * 32, k0 = blockIdx.y * 32;
    const int tx = threadIdx.x, ty = threadIdx.y;
    #pragma unroll
    for (int i = 0; i < 32; i += 8)
        t[ty + i][tx] = W[(size_t)(k0 + ty + i) * N + n0 + tx];
    __syncthreads();
    #pragma unroll
    for (int i = 0; i < 32; i += 8)
        Bh[(size_t)(n0 + ty + i) * K + (k0 + tx)] = __float2half_rn(t[tx][ty + i]);
}

// ---------------------------------------------------------------------------
// fp16-split GEMM via mma.sync:  C[M,N] = A @ B^T + bias
//   A: Ah/Al [M][K] fp16 row-major (hi/lo split); B: [N][K] fp16 row-major
//   2 passes: Ah*B + Al*B  (fp32 accum; B-rounding err ~1.4e-4 RMS)
// Tile 128x128xBK32, 3-stage cp.async pipeline, 256 threads (2m x 4n warps,
// warp tile 64x32), 2 CTAs/SM.
// ---------------------------------------------------------------------------
#define BKC 32
#define STAGE_BYTES 24576            // Ah 8KB + Al 8KB + B 8KB
#define OFF_AH 0
#define OFF_AL 8192
#define OFF_B  16384
#define NSTAGE 3
#define GEMM_SMEM (NSTAGE * STAGE_BYTES)   // 73728
#define NCHUNK (GK / BKC)

__device__ __forceinline__ void issue_stage(uint32_t sbase,
    const __half* __restrict__ Ah, const __half* __restrict__ Al,
    const __half* __restrict__ B, int k0, int tid)
{
    #pragma unroll
    for (int h = 0; h < 2; h++) {
        int idx = tid + h * 256;            // 0..511
        int row = idx >> 2;                 // 0..127
        int kc  = idx & 3;                  // 16B chunk in row
        uint32_t off = tile_off(row, kc * 16);
        size_t g = (size_t)row * GK + k0 + kc * 8;
        CP_ASYNC16(sbase + OFF_AH + off, Ah + g);
        CP_ASYNC16(sbase + OFF_AL + off, Al + g);
        CP_ASYNC16(sbase + OFF_B  + off, B  + g);
    }
}

__global__ __launch_bounds__(256, 2)
void gemm_mma_kernel(const __half* __restrict__ Ah,
                     const __half* __restrict__ Al,
                     const __half* __restrict__ B,
                     const float* __restrict__ bias,
                     float* __restrict__ C, int N)
{
    extern __shared__ char smem[];
    const uint32_t sbase = smem_to_u32(smem);
    const int tid  = threadIdx.x;
    const int lane = tid & 31;
    const int wid  = tid >> 5;
    const int wm   = wid & 1;           // 0..1  (64-row half)
    const int wn   = wid >> 1;          // 0..3  (32-col quarter)
    const int m0 = blockIdx.y * 128;
    const int n0 = blockIdx.x * 128;

    const __half* Ahb = Ah + (size_t)m0 * GK;
    const __half* Alb = Al + (size_t)m0 * GK;
    const __half* Bb  = B  + (size_t)n0 * GK;

    float acc[4][4][4];
    #pragma unroll
    for (int i = 0; i < 4; i++)
        #pragma unroll
        for (int j = 0; j < 4; j++)
            #pragma unroll
            for (int q = 0; q < 4; q++) acc[i][j][q] = 0.f;

    issue_stage(sbase + 0 * STAGE_BYTES, Ahb, Alb, Bb, 0, tid);
    CP_COMMIT();
    issue_stage(sbase + 1 * STAGE_BYTES, Ahb, Alb, Bb, BKC, tid);
    CP_COMMIT();

    const int lrow = lane & 15;
    const int lcol = (lane >> 4) * 16;

    for (int c = 0; c < NCHUNK; c++) {
        if (c + 2 < NCHUNK) CP_WAIT(1); else CP_WAIT(0);
        __syncthreads();

        if (c + 2 < NCHUNK) {
            issue_stage(sbase + ((c + 2) % NSTAGE) * STAGE_BYTES,
                        Ahb, Alb, Bb, (c + 2) * BKC, tid);
            CP_COMMIT();
        }

        const uint32_t sb = sbase + (c % NSTAGE) * STAGE_BYTES;

        #pragma unroll
        for (int ks = 0; ks < 2; ks++) {
            const int kb = ks * 32 + lcol;
            uint32_t ah[4][4], al[4][4];
            #pragma unroll
            for (int mt = 0; mt < 4; mt++) {
                uint32_t o = tile_off(wm * 64 + mt * 16 + lrow, kb);
                ldsm_x4(ah[mt], sb + OFF_AH + o);
                ldsm_x4(al[mt], sb + OFF_AL + o);
            }
            uint32_t bf[2][4];
            #pragma unroll
            for (int ng = 0; ng < 2; ng++) {
                uint32_t o = tile_off(wn * 32 + ng * 16 + lrow, kb);
                ldsm_x4(bf[ng], sb + OFF_B + o);
            }
            #pragma unroll
            for (int mt = 0; mt < 4; mt++)
                #pragma unroll
                for (int nt = 0; nt < 4; nt++)
                    mma_f16(acc[mt][nt], ah[mt],
                            bf[nt >> 1][nt & 1], bf[nt >> 1][(nt & 1) + 2]);
            #pragma unroll
            for (int mt = 0; mt < 4; mt++)
                #pragma unroll
                for (int nt = 0; nt < 4; nt++)
                    mma_f16(acc[mt][nt], al[mt],
                            bf[nt >> 1][nt & 1], bf[nt >> 1][(nt & 1) + 2]);
        }
    }

    // epilogue
    float* Cblk = C + (size_t)m0 * N + n0;
    #pragma unroll
    for (int mt = 0; mt < 4; mt++) {
        #pragma unroll
        for (int nt = 0; nt < 4; nt++) {
            int r  = wm * 64 + mt * 16 + (lane >> 2);
            int cc = wn * 32 + nt * 8 + (lane & 3) * 2;
            float b0 = __ldg(&bias[n0 + cc]);
            float b1 = __ldg(&bias[n0 + cc + 1]);
            float2 v0 = {acc[mt][nt][0] + b0, acc[mt][nt][1] + b1};
            float2 v1 = {acc[mt][nt][2] + b0, acc[mt][nt][3] + b1};
            *(float2*)(Cblk + (size_t)r * N + cc) = v0;
            *(float2*)(Cblk + (size_t)(r + 8) * N + cc) = v1;
        }
    }
}

// ---------------------------------------------------------------------------
// Middle kernel (math verified; emits Q split into fp16 hi/lo):
//   p[n,m,s]  = softmax_m( P[b,n,0,m,s] )
//   Qg[n,d,s] = sum_{m<d} p[n,m,s] * P1[(n+m+1)%N, d-1-m, s];  masked last chunk
// ---------------------------------------------------------------------------
__global__ __launch_bounds__(256)
void middle_kernel(const float* __restrict__ P,
                   __half* __restrict__ Qh,
                   __half* __restrict__ Ql)
{
    __shared__ float sR[30][16][17];

    const int sg = blockIdx.x;
    const int c  = blockIdx.y;
    const int b  = blockIdx.z;
    const int tid = threadIdx.x;
    const int sl = tid & 15;
    const int t  = tid >> 4;

    const long Pbase = (long)b * NTOK * 2048;

    for (int i = tid; i < 30 * 16 * 16; i += 256) {
        int s16 = i & 15;
        int d   = (i >> 4) & 15;
        int u   = i >> 8;
        int tokn = c * DD + u + 1;
        if (tokn >= NTOK) tokn -= NTOK;
        sR[u][d][s16] =
            P[Pbase + (long)tokn * 2048 + 1024 + d * 64 + sg * 16 + s16];
    }
    __syncthreads();

    const int n = c * DD + t;
    const float* p0 = P + Pbase + (long)n * 2048 + sg * 16 + sl;

    float v[16];
    float mx = -1e30f;
    #pragma unroll
    for (int d = 0; d < 16; d++) { v[d] = p0[d * 64]; mx = fmaxf(mx, v[d]); }
    float sum = 0.f;
    #pragma unroll
    for (int d = 0; d < 16; d++) { v[d] = __expf(v[d] - mx); sum += v[d]; }
    const float inv = 1.f / sum;
    #pragma unroll
    for (int d = 0; d < 16; d++) v[d] *= inv;

    const size_t qbase = ((size_t)b * NTOK + n) * 1024 + sg * 16 + sl;
    const bool lastc = (c == NC - 1);

    #pragma unroll
    for (int d = 0; d < 16; d++) {
        float acc = 0.f;
        #pragma unroll
        for (int m = 0; m < d; m++)
            acc += v[m] * sR[t + m][d - 1 - m][sl];
        if (lastc && (t + d >= DD)) acc = 0.f;
        __half h = __float2half_rn(acc);
        __half l = __float2half_rn(acc - __half2float(h));
        Qh[qbase + d * 64] = h;
        Ql[qbase + d * 64] = l;
    }
}

// ---------------------------------------------------------------------------
extern "C" void kernel_launch(void* const* d_in, const int* in_sizes, int n_in,
                              void* d_out, int out_size)
{
    const float* x  = (const float*)d_in[0];   // [4,4096,1024]
    const float* Wr = (const float*)d_in[1];   // [1024,2048]
    const float* br = (const float*)d_in[2];   // [2048]
    const float* Ww = (const float*)d_in[3];   // [1024,1024]
    const float* bw = (const float*)d_in[4];   // [1024]
    float* out = (float*)d_out;                // [4,4096,1024]

    float* P;
    __half *Ah, *Al, *Qh, *Ql, *B1, *B2;
    cudaGetSymbolAddress((void**)&P,  g_P);
    cudaGetSymbolAddress((void**)&Ah, g_Ah);
    cudaGetSymbolAddress((void**)&Al, g_Al);
    cudaGetSymbolAddress((void**)&Qh, g_Qh);
    cudaGetSymbolAddress((void**)&Ql, g_Ql);
    cudaGetSymbolAddress((void**)&B1, g_B1);
    cudaGetSymbolAddress((void**)&B2, g_B2);

    cudaFuncSetAttribute(gemm_mma_kernel,
                         cudaFuncAttributeMaxDynamicSharedMemorySize, GEMM_SMEM);

    // Prep: split activations, round+transpose weights
    split_x_kernel<<<(GM * GK / 4) / 256, 256>>>(x, Ah, Al);
    {
        dim3 blk(32, 8);
        transpose_h_kernel<<<dim3(2048 / 32, 1024 / 32), blk>>>(Wr, B1, GK, 2048);
        transpose_h_kernel<<<dim3(1024 / 32, 1024 / 32), blk>>>(Ww, B2, GK, 1024);
    }
    // GEMM1: P = x @ W_r + b_r   [16384,1024] x [1024,2048]
    {
        dim3 grid(2048 / 128, GM / 128);
        gemm_mma_kernel<<<grid, 256, GEMM_SMEM>>>(Ah, Al, B1, br, P, 2048);
    }
    // Middle: softmax + triangular conv -> Qh/Ql (fp16 split)
    {
        dim3 grid(4, NC, BB);
        middle_kernel<<<grid, 256>>>(P, Qh, Ql);
    }
    // GEMM2: out = Q @ W_w + b_w   [16384,1024] x [1024,1024]
    {
        dim3 grid(1024 / 128, GM / 128);
        gemm_mma_kernel<<<grid, 256, GEMM_SMEM>>>(Qh, Ql, B2, bw, out, 1024);
    }
}

// round 8
// speedup vs baseline: 2.3509x; 1.6610x over previous
#include <cuda_runtime.h>
#include <cuda_bf16.h>
#include <cuda_fp16.h>
#include <cstdint>

// R8 = R7 resubmitted verbatim: R7 bench was an infra failure (container),
// the single-pass fp16 hypothesis is still unmeasured.

// Problem constants
#define BB   4
#define NTOK 4096
#define PD   1024
#define DD   16
#define NC   (NTOK / DD)
#define GK   1024                 // K of both GEMMs
#define GM   (BB * NTOK)          // 16384 rows

// ---------------------------------------------------------------------------
// Scratch (device globals: allocation-free rule)
// ---------------------------------------------------------------------------
__device__ float g_P[(size_t)GM * 2048];        // P  (128 MiB)
__device__ __half g_A[(size_t)GM * GK];         // x fp16 (32 MiB)
__device__ __half g_Q[(size_t)GM * 1024];       // Q fp16
__device__ __half g_B1[2048 * GK];              // W_r^T fp16 [N][K]
__device__ __half g_B2[1024 * GK];              // W_w^T fp16 [N][K]

// ---------------------------------------------------------------------------
// PTX helpers (plain sm_103-legal only: cp.async / ldmatrix / mma.sync)
// ---------------------------------------------------------------------------
__device__ __forceinline__ uint32_t smem_to_u32(const void* p) {
    uint32_t a;
    asm("{ .reg .u64 t; cvta.to.shared.u64 t, %1; cvt.u32.u64 %0, t; }"
        : "=r"(a) : "l"(p));
    return a;
}

#define CP_ASYNC16(saddr, gptr) \
    asm volatile("cp.async.cg.shared.global [%0], [%1], 16;" \
                 :: "r"(saddr), "l"(gptr))
#define CP_COMMIT() asm volatile("cp.async.commit_group;" ::: "memory")
#define CP_WAIT(n)  asm volatile("cp.async.wait_group %0;" :: "n"(n) : "memory")

__device__ __forceinline__ void ldsm_x4(uint32_t (&r)[4], uint32_t addr) {
    asm volatile("ldmatrix.sync.aligned.m8n8.x4.shared.b16 {%0,%1,%2,%3}, [%4];"
                 : "=r"(r[0]), "=r"(r[1]), "=r"(r[2]), "=r"(r[3]) : "r"(addr));
}

__device__ __forceinline__ void mma_f16(float (&d)[4], const uint32_t (&a)[4],
                                        uint32_t b0, uint32_t b1) {
    asm volatile(
        "mma.sync.aligned.m16n8k16.row.col.f32.f16.f16.f32 "
        "{%0,%1,%2,%3}, {%4,%5,%6,%7}, {%8,%9}, {%0,%1,%2,%3};"
        : "+f"(d[0]), "+f"(d[1]), "+f"(d[2]), "+f"(d[3])
        : "r"(a[0]), "r"(a[1]), "r"(a[2]), "r"(a[3]), "r"(b0), "r"(b1));
}

// Swizzled byte offset inside a [rows][64 B] tile.
// 8 consecutive rows at fixed kbyte map to 8 distinct 16B slots mod 128B.
__device__ __forceinline__ uint32_t tile_off(int row, int kbyte) {
    return (uint32_t)(row * 64 + (kbyte ^ (((row >> 1) & 3) << 4)));
}

// ---------------------------------------------------------------------------
// Prep kernels
// ---------------------------------------------------------------------------
__global__ void round_x_kernel(const float* __restrict__ X,
                               __half* __restrict__ H)
{
    size_t i = (size_t)blockIdx.x * blockDim.x + threadIdx.x;   // float4 idx
    float4 v = ((const float4*)X)[i];
    __half h[4];
    h[0] = __float2half_rn(v.x);
    h[1] = __float2half_rn(v.y);
    h[2] = __float2half_rn(v.z);
    h[3] = __float2half_rn(v.w);
    *(uint64_t*)(H + i * 4) = *(uint64_t*)h;
}

// W [K][N] fp32 -> B [N][K] fp16 (transposed, single rounding)
__global__ void transpose_h_kernel(const float* __restrict__ W,
                                   __half* __restrict__ Bh,
                                   int K, int N)
{
    __shared__ float t[32][33];
    const int n0 = blockIdx.x * 32, k0 = blockIdx.y * 32;
    const int tx = threadIdx.x, ty = threadIdx.y;
    #pragma unroll
    for (int i = 0; i < 32; i += 8)
        t[ty + i][tx] = W[(size_t)(k0 + ty + i) * N + n0 + tx];
    __syncthreads();
    #pragma unroll
    for (int i = 0; i < 32; i += 8)
        Bh[(size_t)(n0 + ty + i) * K + (k0 + tx)] = __float2half_rn(t[tx][ty + i]);
}

// ---------------------------------------------------------------------------
// fp16 GEMM via mma.sync:  C[M,N] = A @ B^T + bias   (single pass, fp32 accum)
//   A: [M][K] fp16 row-major;  B: [N][K] fp16 row-major
// Tile 128x128xBK32, 4-stage cp.async pipeline (depth 3 in flight),
// 256 threads (2m x 4n warps, warp tile 64x32), 2 CTAs/SM.
// ---------------------------------------------------------------------------
#define BKC 32
#define STAGE_BYTES 16384            // A 8KB + B 8KB
#define OFF_A 0
#define OFF_B 8192
#define NSTAGE 4
#define GEMM_SMEM (NSTAGE * STAGE_BYTES)   // 65536
#define NCHUNK (GK / BKC)

__device__ __forceinline__ void issue_stage(uint32_t sbase,
    const __half* __restrict__ A, const __half* __restrict__ B,
    int k0, int tid)
{
    #pragma unroll
    for (int h = 0; h < 2; h++) {
        int idx = tid + h * 256;            // 0..511
        int row = idx >> 2;                 // 0..127
        int kc  = idx & 3;                  // 16B chunk in row
        uint32_t off = tile_off(row, kc * 16);
        size_t g = (size_t)row * GK + k0 + kc * 8;
        CP_ASYNC16(sbase + OFF_A + off, A + g);
        CP_ASYNC16(sbase + OFF_B + off, B + g);
    }
}

__global__ __launch_bounds__(256, 2)
void gemm_mma_kernel(const __half* __restrict__ A,
                     const __half* __restrict__ B,
                     const float* __restrict__ bias,
                     float* __restrict__ C, int N)
{
    extern __shared__ char smem[];
    const uint32_t sbase = smem_to_u32(smem);
    const int tid  = threadIdx.x;
    const int lane = tid & 31;
    const int wid  = tid >> 5;
    const int wm   = wid & 1;           // 0..1  (64-row half)
    const int wn   = wid >> 1;          // 0..3  (32-col quarter)
    const int m0 = blockIdx.y * 128;
    const int n0 = blockIdx.x * 128;

    const __half* Ab = A + (size_t)m0 * GK;
    const __half* Bb = B + (size_t)n0 * GK;

    float acc[4][4][4];
    #pragma unroll
    for (int i = 0; i < 4; i++)
        #pragma unroll
        for (int j = 0; j < 4; j++)
            #pragma unroll
            for (int q = 0; q < 4; q++) acc[i][j][q] = 0.f;

    // prologue: 3 stages in flight
    issue_stage(sbase + 0 * STAGE_BYTES, Ab, Bb, 0 * BKC, tid);
    CP_COMMIT();
    issue_stage(sbase + 1 * STAGE_BYTES, Ab, Bb, 1 * BKC, tid);
    CP_COMMIT();
    issue_stage(sbase + 2 * STAGE_BYTES, Ab, Bb, 2 * BKC, tid);
    CP_COMMIT();

    const int lrow = lane & 15;
    const int lcol = (lane >> 4) * 16;

    for (int c = 0; c < NCHUNK; c++) {
        CP_WAIT(2);                       // stage c complete
        __syncthreads();

        if (c + 3 < NCHUNK) {
            issue_stage(sbase + ((c + 3) % NSTAGE) * STAGE_BYTES,
                        Ab, Bb, (c + 3) * BKC, tid);
            CP_COMMIT();
        }

        const uint32_t sb = sbase + (c % NSTAGE) * STAGE_BYTES;

        #pragma unroll
        for (int ks = 0; ks < 2; ks++) {
            const int kb = ks * 32 + lcol;
            uint32_t af[4][4];
            #pragma unroll
            for (int mt = 0; mt < 4; mt++) {
                uint32_t o = tile_off(wm * 64 + mt * 16 + lrow, kb);
                ldsm_x4(af[mt], sb + OFF_A + o);
            }
            uint32_t bf[2][4];
            #pragma unroll
            for (int ng = 0; ng < 2; ng++) {
                uint32_t o = tile_off(wn * 32 + ng * 16 + lrow, kb);
                ldsm_x4(bf[ng], sb + OFF_B + o);
            }
            #pragma unroll
            for (int mt = 0; mt < 4; mt++)
                #pragma unroll
                for (int nt = 0; nt < 4; nt++)
                    mma_f16(acc[mt][nt], af[mt],
                            bf[nt >> 1][nt & 1], bf[nt >> 1][(nt & 1) + 2]);
        }
        __syncthreads();
    }

    // epilogue
    float* Cblk = C + (size_t)m0 * N + n0;
    #pragma unroll
    for (int mt = 0; mt < 4; mt++) {
        #pragma unroll
        for (int nt = 0; nt < 4; nt++) {
            int r  = wm * 64 + mt * 16 + (lane >> 2);
            int cc = wn * 32 + nt * 8 + (lane & 3) * 2;
            float b0 = __ldg(&bias[n0 + cc]);
            float b1 = __ldg(&bias[n0 + cc + 1]);
            float2 v0 = {acc[mt][nt][0] + b0, acc[mt][nt][1] + b1};
            float2 v1 = {acc[mt][nt][2] + b0, acc[mt][nt][3] + b1};
            *(float2*)(Cblk + (size_t)r * N + cc) = v0;
            *(float2*)(Cblk + (size_t)(r + 8) * N + cc) = v1;
        }
    }
}

// ---------------------------------------------------------------------------
// Middle kernel (math verified; emits Q as single fp16):
//   p[n,m,s]  = softmax_m( P[b,n,0,m,s] )
//   Qg[n,d,s] = sum_{m<d} p[n,m,s] * P1[(n+m+1)%N, d-1-m, s];  masked last chunk
// ---------------------------------------------------------------------------
__global__ __launch_bounds__(256)
void middle_kernel(const float* __restrict__ P,
                   __half* __restrict__ Q)
{
    __shared__ float sR[30][16][17];

    const int sg = blockIdx.x;
    const int c  = blockIdx.y;
    const int b  = blockIdx.z;
    const int tid = threadIdx.x;
    const int sl = tid & 15;
    const int t  = tid >> 4;

    const long Pbase = (long)b * NTOK * 2048;

    for (int i = tid; i < 30 * 16 * 16; i += 256) {
        int s16 = i & 15;
        int d   = (i >> 4) & 15;
        int u   = i >> 8;
        int tokn = c * DD + u + 1;
        if (tokn >= NTOK) tokn -= NTOK;
        sR[u][d][s16] =
            P[Pbase + (long)tokn * 2048 + 1024 + d * 64 + sg * 16 + s16];
    }
    __syncthreads();

    const int n = c * DD + t;
    const float* p0 = P + Pbase + (long)n * 2048 + sg * 16 + sl;

    float v[16];
    float mx = -1e30f;
    #pragma unroll
    for (int d = 0; d < 16; d++) { v[d] = p0[d * 64]; mx = fmaxf(mx, v[d]); }
    float sum = 0.f;
    #pragma unroll
    for (int d = 0; d < 16; d++) { v[d] = __expf(v[d] - mx); sum += v[d]; }
    const float inv = 1.f / sum;
    #pragma unroll
    for (int d = 0; d < 16; d++) v[d] *= inv;

    const size_t qbase = ((size_t)b * NTOK + n) * 1024 + sg * 16 + sl;
    const bool lastc = (c == NC - 1);

    #pragma unroll
    for (int d = 0; d < 16; d++) {
        float acc = 0.f;
        #pragma unroll
        for (int m = 0; m < d; m++)
            acc += v[m] * sR[t + m][d - 1 - m][sl];
        if (lastc && (t + d >= DD)) acc = 0.f;
        Q[qbase + d * 64] = __float2half_rn(acc);
    }
}

// ---------------------------------------------------------------------------
extern "C" void kernel_launch(void* const* d_in, const int* in_sizes, int n_in,
                              void* d_out, int out_size)
{
    const float* x  = (const float*)d_in[0];   // [4,4096,1024]
    const float* Wr = (const float*)d_in[1];   // [1024,2048]
    const float* br = (const float*)d_in[2];   // [2048]
    const float* Ww = (const float*)d_in[3];   // [1024,1024]
    const float* bw = (const float*)d_in[4];   // [1024]
    float* out = (float*)d_out;                // [4,4096,1024]

    float* P;
    __half *A, *Q, *B1, *B2;
    cudaGetSymbolAddress((void**)&P,  g_P);
    cudaGetSymbolAddress((void**)&A,  g_A);
    cudaGetSymbolAddress((void**)&Q,  g_Q);
    cudaGetSymbolAddress((void**)&B1, g_B1);
    cudaGetSymbolAddress((void**)&B2, g_B2);

    cudaFuncSetAttribute(gemm_mma_kernel,
                         cudaFuncAttributeMaxDynamicSharedMemorySize, GEMM_SMEM);

    // Prep: round activations, round+transpose weights
    round_x_kernel<<<(GM * GK / 4) / 256, 256>>>(x, A);
    {
        dim3 blk(32, 8);
        transpose_h_kernel<<<dim3(2048 / 32, 1024 / 32), blk>>>(Wr, B1, GK, 2048);
        transpose_h_kernel<<<dim3(1024 / 32, 1024 / 32), blk>>>(Ww, B2, GK, 1024);
    }
    // GEMM1: P = x @ W_r + b_r   [16384,1024] x [1024,2048]
    {
        dim3 grid(2048 / 128, GM / 128);
        gemm_mma_kernel<<<grid, 256, GEMM_SMEM>>>(A, B1, br, P, 2048);
    }
    // Middle: softmax + triangular conv -> Q (fp16)
    {
        dim3 grid(4, NC, BB);
        middle_kernel<<<grid, 256>>>(P, Q);
    }
    // GEMM2: out = Q @ W_w + b_w   [16384,1024] x [1024,1024]
    {
        dim3 grid(1024 / 128, GM / 128);
        gemm_mma_kernel<<<grid, 256, GEMM_SMEM>>>(Q, B2, bw, out, 1024);
    }
}

// round 10
// speedup vs baseline: 2.5522x; 1.0856x over previous
#include <cuda_runtime.h>
#include <cuda_bf16.h>
#include <cuda_fp16.h>
#include <cstdint>

// Problem constants
#define BB   4
#define NTOK 4096
#define PD   1024
#define DD   16
#define NC   (NTOK / DD)
#define GK   1024                 // K of both GEMMs
#define GM   (BB * NTOK)          // 16384 rows

// ---------------------------------------------------------------------------
// Scratch (device globals: allocation-free rule)
// ---------------------------------------------------------------------------
__device__ float g_P[(size_t)GM * 2048];        // P  (128 MiB)
__device__ __half g_A[(size_t)GM * GK];         // x fp16 (32 MiB)
__device__ __half g_Q[(size_t)GM * 1024];       // Q fp16
__device__ __half g_B1[2048 * GK];              // W_r^T fp16 [N][K]
__device__ __half g_B2[1024 * GK];              // W_w^T fp16 [N][K]

// ---------------------------------------------------------------------------
// PTX helpers (plain sm_103-legal only: cp.async / ldmatrix / mma.sync)
// ---------------------------------------------------------------------------
__device__ __forceinline__ uint32_t smem_to_u32(const void* p) {
    uint32_t a;
    asm("{ .reg .u64 t; cvta.to.shared.u64 t, %1; cvt.u32.u64 %0, t; }"
        : "=r"(a) : "l"(p));
    return a;
}

#define CP_ASYNC16(saddr, gptr) \
    asm volatile("cp.async.cg.shared.global [%0], [%1], 16;" \
                 :: "r"(saddr), "l"(gptr))
#define CP_COMMIT() asm volatile("cp.async.commit_group;" ::: "memory")
#define CP_WAIT(n)  asm volatile("cp.async.wait_group %0;" :: "n"(n) : "memory")

__device__ __forceinline__ void ldsm_x4(uint32_t (&r)[4], uint32_t addr) {
    asm volatile("ldmatrix.sync.aligned.m8n8.x4.shared.b16 {%0,%1,%2,%3}, [%4];"
                 : "=r"(r[0]), "=r"(r[1]), "=r"(r[2]), "=r"(r[3]) : "r"(addr));
}

__device__ __forceinline__ void mma_f16(float (&d)[4], const uint32_t (&a)[4],
                                        uint32_t b0, uint32_t b1) {
    asm volatile(
        "mma.sync.aligned.m16n8k16.row.col.f32.f16.f16.f32 "
        "{%0,%1,%2,%3}, {%4,%5,%6,%7}, {%8,%9}, {%0,%1,%2,%3};"
        : "+f"(d[0]), "+f"(d[1]), "+f"(d[2]), "+f"(d[3])
        : "r"(a[0]), "r"(a[1]), "r"(a[2]), "r"(a[3]), "r"(b0), "r"(b1));
}

// SW128 swizzle for [rows][128 B] tiles: 8 consecutive rows at a fixed kbyte
// map to 8 distinct 16B slots within the 128B line.
__device__ __forceinline__ uint32_t tile_off128(int row, int kbyte) {
    return (uint32_t)(row * 128 + (kbyte ^ ((row & 7) << 4)));
}

// ---------------------------------------------------------------------------
// Prep kernels
// ---------------------------------------------------------------------------
__global__ void round_x_kernel(const float* __restrict__ X,
                               __half* __restrict__ H)
{
    size_t i = (size_t)blockIdx.x * blockDim.x + threadIdx.x;   // float4 idx
    float4 v = ((const float4*)X)[i];
    __half h[4];
    h[0] = __float2half_rn(v.x);
    h[1] = __float2half_rn(v.y);
    h[2] = __float2half_rn(v.z);
    h[3] = __float2half_rn(v.w);
    *(uint64_t*)(H + i * 4) = *(uint64_t*)h;
}

// W [K][N] fp32 -> B [N][K] fp16 (transposed, single rounding)
__global__ void transpose_h_kernel(const float* __restrict__ W,
                                   __half* __restrict__ Bh,
                                   int K, int N)
{
    __shared__ float t[32][33];
    const int n0 = blockIdx.x * 32, k0 = blockIdx.y * 32;
    const int tx = threadIdx.x, ty = threadIdx.y;
    #pragma unroll
    for (int i = 0; i < 32; i += 8)
        t[ty + i][tx] = W[(size_t)(k0 + ty + i) * N + n0 + tx];
    __syncthreads();
    #pragma unroll
    for (int i = 0; i < 32; i += 8)
        Bh[(size_t)(n0 + ty + i) * K + (k0 + tx)] = __float2half_rn(t[tx][ty + i]);
}

// ---------------------------------------------------------------------------
// fp16 GEMM via mma.sync:  C[M,N] = A @ B^T + bias   (single pass, fp32 accum)
//   A: [M][K] fp16 row-major;  B: [N][K] fp16 row-major
// Tile 128x128xBK64, 3-stage cp.async pipeline, 256 threads
// (2m x 4n warps, warp tile 64x32), 2 CTAs/SM. 16 mainloop iterations,
// one barrier per 64-K chunk.
// ---------------------------------------------------------------------------
#define BKC 64
#define STAGE_BYTES 32768            // A 16KB + B 16KB
#define OFF_A 0
#define OFF_B 16384
#define NSTAGE 3
#define GEMM_SMEM (NSTAGE * STAGE_BYTES)   // 98304
#define NCHUNK (GK / BKC)                  // 16

__device__ __forceinline__ void issue_stage(uint32_t sbase,
    const __half* __restrict__ A, const __half* __restrict__ B,
    int k0, int tid)
{
    // A and B tiles: 128 rows x 128B each = 1024 x 16B granules each
    #pragma unroll
    for (int h = 0; h < 4; h++) {
        int idx = tid + h * 256;            // 0..1023
        int row = idx >> 3;                 // 0..127
        int kc  = idx & 7;                  // 16B chunk in 128B row
        uint32_t off = tile_off128(row, kc * 16);
        size_t g = (size_t)row * GK + k0 + kc * 8;
        CP_ASYNC16(sbase + OFF_A + off, A + g);
        CP_ASYNC16(sbase + OFF_B + off, B + g);
    }
}

__global__ __launch_bounds__(256, 2)
void gemm_mma_kernel(const __half* __restrict__ A,
                     const __half* __restrict__ B,
                     const float* __restrict__ bias,
                     float* __restrict__ C, int N)
{
    extern __shared__ char smem[];
    const uint32_t sbase = smem_to_u32(smem);
    const int tid  = threadIdx.x;
    const int lane = tid & 31;
    const int wid  = tid >> 5;
    const int wm   = wid & 1;           // 0..1  (64-row half)
    const int wn   = wid >> 1;          // 0..3  (32-col quarter)
    const int m0 = blockIdx.y * 128;
    const int n0 = blockIdx.x * 128;

    const __half* Ab = A + (size_t)m0 * GK;
    const __half* Bb = B + (size_t)n0 * GK;

    float acc[4][4][4];
    #pragma unroll
    for (int i = 0; i < 4; i++)
        #pragma unroll
        for (int j = 0; j < 4; j++)
            #pragma unroll
            for (int q = 0; q < 4; q++) acc[i][j][q] = 0.f;

    // prologue: 2 stages in flight
    issue_stage(sbase + 0 * STAGE_BYTES, Ab, Bb, 0 * BKC, tid);
    CP_COMMIT();
    issue_stage(sbase + 1 * STAGE_BYTES, Ab, Bb, 1 * BKC, tid);
    CP_COMMIT();

    const int lrow = lane & 15;
    const int lcol = (lane >> 4) * 16;

    for (int c = 0; c < NCHUNK; c++) {
        if (c + 2 < NCHUNK) CP_WAIT(1); else CP_WAIT(0);
        __syncthreads();
        // Write target (c+2)%3 == buffer of chunk c-1; all warps finished
        // reading it before passing the barrier above. No trailing barrier
        // needed for the same reason.
        if (c + 2 < NCHUNK) {
            issue_stage(sbase + ((c + 2) % NSTAGE) * STAGE_BYTES,
                        Ab, Bb, (c + 2) * BKC, tid);
            CP_COMMIT();
        }

        const uint32_t sb = sbase + (c % NSTAGE) * STAGE_BYTES;

        #pragma unroll
        for (int ks = 0; ks < 4; ks++) {
            const int kb = ks * 32 + lcol;
            uint32_t af[4][4];
            #pragma unroll
            for (int mt = 0; mt < 4; mt++) {
                uint32_t o = tile_off128(wm * 64 + mt * 16 + lrow, kb);
                ldsm_x4(af[mt], sb + OFF_A + o);
            }
            uint32_t bf[2][4];
            #pragma unroll
            for (int ng = 0; ng < 2; ng++) {
                uint32_t o = tile_off128(wn * 32 + ng * 16 + lrow, kb);
                ldsm_x4(bf[ng], sb + OFF_B + o);
            }
            #pragma unroll
            for (int mt = 0; mt < 4; mt++)
                #pragma unroll
                for (int nt = 0; nt < 4; nt++)
                    mma_f16(acc[mt][nt], af[mt],
                            bf[nt >> 1][nt & 1], bf[nt >> 1][(nt & 1) + 2]);
        }
    }

    // epilogue
    float* Cblk = C + (size_t)m0 * N + n0;
    #pragma unroll
    for (int mt = 0; mt < 4; mt++) {
        #pragma unroll
        for (int nt = 0; nt < 4; nt++) {
            int r  = wm * 64 + mt * 16 + (lane >> 2);
            int cc = wn * 32 + nt * 8 + (lane & 3) * 2;
            float b0 = __ldg(&bias[n0 + cc]);
            float b1 = __ldg(&bias[n0 + cc + 1]);
            float2 v0 = {acc[mt][nt][0] + b0, acc[mt][nt][1] + b1};
            float2 v1 = {acc[mt][nt][2] + b0, acc[mt][nt][3] + b1};
            *(float2*)(Cblk + (size_t)r * N + cc) = v0;
            *(float2*)(Cblk + (size_t)(r + 8) * N + cc) = v1;
        }
    }
}

// ---------------------------------------------------------------------------
// Middle kernel (math verified; emits Q as single fp16):
//   p[n,m,s]  = softmax_m( P[b,n,0,m,s] )
//   Qg[n,d,s] = sum_{m<d} p[n,m,s] * P1[(n+m+1)%N, d-1-m, s];  masked last chunk
// ---------------------------------------------------------------------------
__global__ __launch_bounds__(256)
void middle_kernel(const float* __restrict__ P,
                   __half* __restrict__ Q)
{
    __shared__ float sR[30][16][17];

    const int sg = blockIdx.x;
    const int c  = blockIdx.y;
    const int b  = blockIdx.z;
    const int tid = threadIdx.x;
    const int sl = tid & 15;
    const int t  = tid >> 4;

    const long Pbase = (long)b * NTOK * 2048;

    for (int i = tid; i < 30 * 16 * 16; i += 256) {
        int s16 = i & 15;
        int d   = (i >> 4) & 15;
        int u   = i >> 8;
        int tokn = c * DD + u + 1;
        if (tokn >= NTOK) tokn -= NTOK;
        sR[u][d][s16] =
            P[Pbase + (long)tokn * 2048 + 1024 + d * 64 + sg * 16 + s16];
    }
    __syncthreads();

    const int n = c * DD + t;
    const float* p0 = P + Pbase + (long)n * 2048 + sg * 16 + sl;

    float v[16];
    float mx = -1e30f;
    #pragma unroll
    for (int d = 0; d < 16; d++) { v[d] = p0[d * 64]; mx = fmaxf(mx, v[d]); }
    float sum = 0.f;
    #pragma unroll
    for (int d = 0; d < 16; d++) { v[d] = __expf(v[d] - mx); sum += v[d]; }
    const float inv = 1.f / sum;
    #pragma unroll
    for (int d = 0; d < 16; d++) v[d] *= inv;

    const size_t qbase = ((size_t)b * NTOK + n) * 1024 + sg * 16 + sl;
    const bool lastc = (c == NC - 1);

    #pragma unroll
    for (int d = 0; d < 16; d++) {
        float acc = 0.f;
        #pragma unroll
        for (int m = 0; m < d; m++)
            acc += v[m] * sR[t + m][d - 1 - m][sl];
        if (lastc && (t + d >= DD)) acc = 0.f;
        Q[qbase + d * 64] = __float2half_rn(acc);
    }
}

// ---------------------------------------------------------------------------
extern "C" void kernel_launch(void* const* d_in, const int* in_sizes, int n_in,
                              void* d_out, int out_size)
{
    const float* x  = (const float*)d_in[0];   // [4,4096,1024]
    const float* Wr = (const float*)d_in[1];   // [1024,2048]
    const float* br = (const float*)d_in[2];   // [2048]
    const float* Ww = (const float*)d_in[3];   // [1024,1024]
    const float* bw = (const float*)d_in[4];   // [1024]
    float* out = (float*)d_out;                // [4,4096,1024]

    float* P;
    __half *A, *Q, *B1, *B2;
    cudaGetSymbolAddress((void**)&P,  g_P);
    cudaGetSymbolAddress((void**)&A,  g_A);
    cudaGetSymbolAddress((void**)&Q,  g_Q);
    cudaGetSymbolAddress((void**)&B1, g_B1);
    cudaGetSymbolAddress((void**)&B2, g_B2);

    cudaFuncSetAttribute(gemm_mma_kernel,
                         cudaFuncAttributeMaxDynamicSharedMemorySize, GEMM_SMEM);

    // Prep: round activations, round+transpose weights
    round_x_kernel<<<(GM * GK / 4) / 256, 256>>>(x, A);
    {
        dim3 blk(32, 8);
        transpose_h_kernel<<<dim3(2048 / 32, 1024 / 32), blk>>>(Wr, B1, GK, 2048);
        transpose_h_kernel<<<dim3(1024 / 32, 1024 / 32), blk>>>(Ww, B2, GK, 1024);
    }
    // GEMM1: P = x @ W_r + b_r   [16384,1024] x [1024,2048]
    {
        dim3 grid(2048 / 128, GM / 128);
        gemm_mma_kernel<<<grid, 256, GEMM_SMEM>>>(A, B1, br, P, 2048);
    }
    // Middle: softmax + triangular conv -> Q (fp16)
    {
        dim3 grid(4, NC, BB);
        middle_kernel<<<grid, 256>>>(P, Q);
    }
    // GEMM2: out = Q @ W_w + b_w   [16384,1024] x [1024,1024]
    {
        dim3 grid(1024 / 128, GM / 128);
        gemm_mma_kernel<<<grid, 256, GEMM_SMEM>>>(Q, B2, bw, out, 1024);
    }
}

// round 11
// speedup vs baseline: 2.6012x; 1.0192x over previous
#include <cuda_runtime.h>
#include <cuda_bf16.h>
#include <cuda_fp16.h>
#include <cstdint>

// Problem constants
#define BB   4
#define NTOK 4096
#define PD   1024
#define DD   16
#define NC   (NTOK / DD)
#define GK   1024                 // K of both GEMMs
#define GM   (BB * NTOK)          // 16384 rows

// ---------------------------------------------------------------------------
// Scratch (device globals: allocation-free rule)
// ---------------------------------------------------------------------------
__device__ float  g_PL[(size_t)GM * 1024];      // P logits half (fp32, 64 MiB)
__device__ __half g_PR[(size_t)GM * 1024];      // P window half (fp16, 32 MiB)
__device__ __half g_A[(size_t)GM * GK];         // x fp16 (32 MiB)
__device__ __half g_Q[(size_t)GM * 1024];       // Q fp16
__device__ __half g_B1[2048 * GK];              // W_r^T fp16 [N][K]
__device__ __half g_B2[1024 * GK];              // W_w^T fp16 [N][K]

// ---------------------------------------------------------------------------
// PTX helpers (plain sm_103-legal only: cp.async / ldmatrix / mma.sync)
// ---------------------------------------------------------------------------
__device__ __forceinline__ uint32_t smem_to_u32(const void* p) {
    uint32_t a;
    asm("{ .reg .u64 t; cvta.to.shared.u64 t, %1; cvt.u32.u64 %0, t; }"
        : "=r"(a) : "l"(p));
    return a;
}

#define CP_ASYNC16(saddr, gptr) \
    asm volatile("cp.async.cg.shared.global [%0], [%1], 16;" \
                 :: "r"(saddr), "l"(gptr))
#define CP_COMMIT() asm volatile("cp.async.commit_group;" ::: "memory")
#define CP_WAIT(n)  asm volatile("cp.async.wait_group %0;" :: "n"(n) : "memory")

__device__ __forceinline__ void ldsm_x4(uint32_t (&r)[4], uint32_t addr) {
    asm volatile("ldmatrix.sync.aligned.m8n8.x4.shared.b16 {%0,%1,%2,%3}, [%4];"
                 : "=r"(r[0]), "=r"(r[1]), "=r"(r[2]), "=r"(r[3]) : "r"(addr));
}

__device__ __forceinline__ void mma_f16(float (&d)[4], const uint32_t (&a)[4],
                                        uint32_t b0, uint32_t b1) {
    asm volatile(
        "mma.sync.aligned.m16n8k16.row.col.f32.f16.f16.f32 "
        "{%0,%1,%2,%3}, {%4,%5,%6,%7}, {%8,%9}, {%0,%1,%2,%3};"
        : "+f"(d[0]), "+f"(d[1]), "+f"(d[2]), "+f"(d[3])
        : "r"(a[0]), "r"(a[1]), "r"(a[2]), "r"(a[3]), "r"(b0), "r"(b1));
}

// SW128 swizzle for [rows][128 B] tiles.
__device__ __forceinline__ uint32_t tile_off128(int row, int kbyte) {
    return (uint32_t)(row * 128 + (kbyte ^ ((row & 7) << 4)));
}

// ---------------------------------------------------------------------------
// Prep kernels
// ---------------------------------------------------------------------------
__global__ void round_x_kernel(const float* __restrict__ X,
                               __half* __restrict__ H)
{
    size_t i = (size_t)blockIdx.x * blockDim.x + threadIdx.x;   // float4 idx
    float4 v = ((const float4*)X)[i];
    __half h[4];
    h[0] = __float2half_rn(v.x);
    h[1] = __float2half_rn(v.y);
    h[2] = __float2half_rn(v.z);
    h[3] = __float2half_rn(v.w);
    *(uint64_t*)(H + i * 4) = *(uint64_t*)h;
}

// W [K][N] fp32 -> B [N][K] fp16 (transposed, single rounding)
__global__ void transpose_h_kernel(const float* __restrict__ W,
                                   __half* __restrict__ Bh,
                                   int K, int N)
{
    __shared__ float t[32][33];
    const int n0 = blockIdx.x * 32, k0 = blockIdx.y * 32;
    const int tx = threadIdx.x, ty = threadIdx.y;
    #pragma unroll
    for (int i = 0; i < 32; i += 8)
        t[ty + i][tx] = W[(size_t)(k0 + ty + i) * N + n0 + tx];
    __syncthreads();
    #pragma unroll
    for (int i = 0; i < 32; i += 8)
        Bh[(size_t)(n0 + ty + i) * K + (k0 + tx)] = __float2half_rn(t[tx][ty + i]);
}

// ---------------------------------------------------------------------------
// fp16 GEMM via mma.sync:  C = A @ B^T + bias   (single pass, fp32 accum)
//   A: [M][K] fp16 row-major;  B: [N][K] fp16 row-major
// Output split: columns [0, nsplit) -> C32 (fp32, row stride nsplit);
//               columns [nsplit, N) -> C16 (fp16, row stride N-nsplit).
// Tile 128x128xBK64, 3-stage cp.async pipeline, 256 threads
// (2m x 4n warps, warp tile 64x32), 2 CTAs/SM.
// ---------------------------------------------------------------------------
#define BKC 64
#define STAGE_BYTES 32768            // A 16KB + B 16KB
#define OFF_A 0
#define OFF_B 16384
#define NSTAGE 3
#define GEMM_SMEM (NSTAGE * STAGE_BYTES)   // 98304
#define NCHUNK (GK / BKC)                  // 16

__device__ __forceinline__ void issue_stage(uint32_t sbase,
    const __half* __restrict__ A, const __half* __restrict__ B,
    int k0, int tid)
{
    #pragma unroll
    for (int h = 0; h < 4; h++) {
        int idx = tid + h * 256;            // 0..1023
        int row = idx >> 3;                 // 0..127
        int kc  = idx & 7;                  // 16B chunk in 128B row
        uint32_t off = tile_off128(row, kc * 16);
        size_t g = (size_t)row * GK + k0 + kc * 8;
        CP_ASYNC16(sbase + OFF_A + off, A + g);
        CP_ASYNC16(sbase + OFF_B + off, B + g);
    }
}

__global__ __launch_bounds__(256, 2)
void gemm_mma_kernel(const __half* __restrict__ A,
                     const __half* __restrict__ B,
                     const float* __restrict__ bias,
                     float* __restrict__ C32,
                     __half* __restrict__ C16,
                     int N, int nsplit)
{
    extern __shared__ char smem[];
    const uint32_t sbase = smem_to_u32(smem);
    const int tid  = threadIdx.x;
    const int lane = tid & 31;
    const int wid  = tid >> 5;
    const int wm   = wid & 1;           // 0..1  (64-row half)
    const int wn   = wid >> 1;          // 0..3  (32-col quarter)
    const int m0 = blockIdx.y * 128;
    const int n0 = blockIdx.x * 128;

    const __half* Ab = A + (size_t)m0 * GK;
    const __half* Bb = B + (size_t)n0 * GK;

    float acc[4][4][4];
    #pragma unroll
    for (int i = 0; i < 4; i++)
        #pragma unroll
        for (int j = 0; j < 4; j++)
            #pragma unroll
            for (int q = 0; q < 4; q++) acc[i][j][q] = 0.f;

    // prologue: 2 stages in flight
    issue_stage(sbase + 0 * STAGE_BYTES, Ab, Bb, 0 * BKC, tid);
    CP_COMMIT();
    issue_stage(sbase + 1 * STAGE_BYTES, Ab, Bb, 1 * BKC, tid);
    CP_COMMIT();

    const int lrow = lane & 15;
    const int lcol = (lane >> 4) * 16;

    for (int c = 0; c < NCHUNK; c++) {
        if (c + 2 < NCHUNK) CP_WAIT(1); else CP_WAIT(0);
        __syncthreads();
        // Buffer (c+2)%3 was last read as chunk c-1, finished by all warps
        // before the barrier above.

        const uint32_t sb = sbase + (c % NSTAGE) * STAGE_BYTES;

        #pragma unroll
        for (int ks = 0; ks < 4; ks++) {
            const int kb = ks * 32 + lcol;
            uint32_t af[4][4];
            #pragma unroll
            for (int mt = 0; mt < 4; mt++) {
                uint32_t o = tile_off128(wm * 64 + mt * 16 + lrow, kb);
                ldsm_x4(af[mt], sb + OFF_A + o);
            }
            uint32_t bf[2][4];
            #pragma unroll
            for (int ng = 0; ng < 2; ng++) {
                uint32_t o = tile_off128(wn * 32 + ng * 16 + lrow, kb);
                ldsm_x4(bf[ng], sb + OFF_B + o);
            }
            #pragma unroll
            for (int mt = 0; mt < 4; mt++)
                #pragma unroll
                for (int nt = 0; nt < 4; nt++)
                    mma_f16(acc[mt][nt], af[mt],
                            bf[nt >> 1][nt & 1], bf[nt >> 1][(nt & 1) + 2]);

            // Issue next stage AFTER the first MMA block so the tensor pipe
            // is busy while the LSU burst drains.
            if (ks == 0 && c + 2 < NCHUNK) {
                issue_stage(sbase + ((c + 2) % NSTAGE) * STAGE_BYTES,
                            Ab, Bb, (c + 2) * BKC, tid);
                CP_COMMIT();
            }
        }
    }

    // epilogue: fp32 columns < nsplit, fp16 columns >= nsplit
    if (n0 < nsplit) {
        float* Cblk = C32 + (size_t)m0 * nsplit + n0;
        #pragma unroll
        for (int mt = 0; mt < 4; mt++) {
            #pragma unroll
            for (int nt = 0; nt < 4; nt++) {
                int r  = wm * 64 + mt * 16 + (lane >> 2);
                int cc = wn * 32 + nt * 8 + (lane & 3) * 2;
                float b0 = __ldg(&bias[n0 + cc]);
                float b1 = __ldg(&bias[n0 + cc + 1]);
                float2 v0 = {acc[mt][nt][0] + b0, acc[mt][nt][1] + b1};
                float2 v1 = {acc[mt][nt][2] + b0, acc[mt][nt][3] + b1};
                *(float2*)(Cblk + (size_t)r * nsplit + cc) = v0;
                *(float2*)(Cblk + (size_t)(r + 8) * nsplit + cc) = v1;
            }
        }
    } else {
        const int w16 = N - nsplit;
        __half* Cblk = C16 + (size_t)m0 * w16 + (n0 - nsplit);
        #pragma unroll
        for (int mt = 0; mt < 4; mt++) {
            #pragma unroll
            for (int nt = 0; nt < 4; nt++) {
                int r  = wm * 64 + mt * 16 + (lane >> 2);
                int cc = wn * 32 + nt * 8 + (lane & 3) * 2;
                float b0 = __ldg(&bias[n0 + cc]);
                float b1 = __ldg(&bias[n0 + cc + 1]);
                __half2 h0 = __floats2half2_rn(acc[mt][nt][0] + b0,
                                               acc[mt][nt][1] + b1);
                __half2 h1 = __floats2half2_rn(acc[mt][nt][2] + b0,
                                               acc[mt][nt][3] + b1);
                *(__half2*)(Cblk + (size_t)r * w16 + cc) = h0;
                *(__half2*)(Cblk + (size_t)(r + 8) * w16 + cc) = h1;
            }
        }
    }
}

// ---------------------------------------------------------------------------
// Middle kernel (math verified through R10; now reads L fp32 / R fp16):
//   p[n,m,s]  = softmax_m( PL[b,n,m,s] )
//   Qg[n,d,s] = sum_{m<d} p[n,m,s] * PR[(n+m+1)%N, d-1-m, s];  masked last chunk
// ---------------------------------------------------------------------------
__global__ __launch_bounds__(256)
void middle_kernel(const float* __restrict__ PL,
                   const __half* __restrict__ PR,
                   __half* __restrict__ Q)
{
    __shared__ float sR[30][16][17];

    const int sg = blockIdx.x;
    const int c  = blockIdx.y;
    const int b  = blockIdx.z;
    const int tid = threadIdx.x;
    const int sl = tid & 15;
    const int t  = tid >> 4;

    const size_t base = (size_t)b * NTOK;

    for (int i = tid; i < 30 * 16 * 16; i += 256) {
        int s16 = i & 15;
        int d   = (i >> 4) & 15;
        int u   = i >> 8;
        int tokn = c * DD + u + 1;
        if (tokn >= NTOK) tokn -= NTOK;
        sR[u][d][s16] =
            __half2float(PR[(base + tokn) * 1024 + d * 64 + sg * 16 + s16]);
    }
    __syncthreads();

    const int n = c * DD + t;
    const float* p0 = PL + (base + n) * 1024 + sg * 16 + sl;

    float v[16];
    float mx = -1e30f;
    #pragma unroll
    for (int d = 0; d < 16; d++) { v[d] = p0[d * 64]; mx = fmaxf(mx, v[d]); }
    float sum = 0.f;
    #pragma unroll
    for (int d = 0; d < 16; d++) { v[d] = __expf(v[d] - mx); sum += v[d]; }
    const float inv = 1.f / sum;
    #pragma unroll
    for (int d = 0; d < 16; d++) v[d] *= inv;

    const size_t qbase = (base + n) * 1024 + sg * 16 + sl;
    const bool lastc = (c == NC - 1);

    #pragma unroll
    for (int d = 0; d < 16; d++) {
        float acc = 0.f;
        #pragma unroll
        for (int m = 0; m < d; m++)
            acc += v[m] * sR[t + m][d - 1 - m][sl];
        if (lastc && (t + d >= DD)) acc = 0.f;
        Q[qbase + d * 64] = __float2half_rn(acc);
    }
}

// ---------------------------------------------------------------------------
extern "C" void kernel_launch(void* const* d_in, const int* in_sizes, int n_in,
                              void* d_out, int out_size)
{
    const float* x  = (const float*)d_in[0];   // [4,4096,1024]
    const float* Wr = (const float*)d_in[1];   // [1024,2048]
    const float* br = (const float*)d_in[2];   // [2048]
    const float* Ww = (const float*)d_in[3];   // [1024,1024]
    const float* bw = (const float*)d_in[4];   // [1024]
    float* out = (float*)d_out;                // [4,4096,1024]

    float* PL;
    __half *PR, *A, *Q, *B1, *B2;
    cudaGetSymbolAddress((void**)&PL, g_PL);
    cudaGetSymbolAddress((void**)&PR, g_PR);
    cudaGetSymbolAddress((void**)&A,  g_A);
    cudaGetSymbolAddress((void**)&Q,  g_Q);
    cudaGetSymbolAddress((void**)&B1, g_B1);
    cudaGetSymbolAddress((void**)&B2, g_B2);

    cudaFuncSetAttribute(gemm_mma_kernel,
                         cudaFuncAttributeMaxDynamicSharedMemorySize, GEMM_SMEM);

    // Prep: round activations, round+transpose weights
    round_x_kernel<<<(GM * GK / 4) / 256, 256>>>(x, A);
    {
        dim3 blk(32, 8);
        transpose_h_kernel<<<dim3(2048 / 32, 1024 / 32), blk>>>(Wr, B1, GK, 2048);
        transpose_h_kernel<<<dim3(1024 / 32, 1024 / 32), blk>>>(Ww, B2, GK, 1024);
    }
    // GEMM1: P = x @ W_r + b_r; cols [0,1024) -> PL fp32, [1024,2048) -> PR fp16
    {
        dim3 grid(2048 / 128, GM / 128);
        gemm_mma_kernel<<<grid, 256, GEMM_SMEM>>>(A, B1, br, PL, PR, 2048, 1024);
    }
    // Middle: softmax + triangular conv -> Q (fp16)
    {
        dim3 grid(4, NC, BB);
        middle_kernel<<<grid, 256>>>(PL, PR, Q);
    }
    // GEMM2: out = Q @ W_w + b_w (all columns fp32)
    {
        dim3 grid(1024 / 128, GM / 128);
        gemm_mma_kernel<<<grid, 256, GEMM_SMEM>>>(Q, B2, bw, out, (__half*)Q,
                                                  1024, 1024);
    }
}